// round 3
// baseline (speedup 1.0000x reference)
#include <cuda_runtime.h>
#include <cstdint>

typedef unsigned long long u64;

// ---------------- folded-parameter block layout (floats) ----------------
#define OFF_PROTO 0      // 10 x 8
#define OFF_P2    80     // 10 (+2 pad)
#define OFF_A     96     // 2 x 10 x 12 (row-padded 10->12): diag(ln1_g) @ Wv @ Wo
#define OFF_AB    336    // 2 x 12: folded attention bias
#define OFF_W1    360    // 2 x 10 x 64: diag(ln2_g) @ W1
#define OFF_B1    1640   // 2 x 64: b1 + ln2_b @ W1
#define OFF_W2    1768   // 2 x 64 x 12 (row-padded 10->12)
#define OFF_B2    3304   // 2 x 12
#define OFF_WC    3328   // 12
#define OFF_BC    3340   // 1
#define NPAR      3344

// float4-unit offsets
#define F4_PROTO  0      // 20 float4
#define F4_P2     20     // 3
#define F4_A      24     // layer stride 30, row stride 3
#define F4_AB     84     // layer stride 3
#define F4_W1     90     // layer stride 160, row stride 16
#define F4_B1     410    // layer stride 16
#define F4_W2     442    // layer stride 192, row stride 3
#define F4_B2     826    // layer stride 3
#define F4_WC     832    // 3
#define F4_BC     835    // .x

__device__ float g_par[NPAR];                      // staging (written by fold kernel)
__constant__ __align__(16) float4 c_par[NPAR / 4]; // hot copy on the constant port

// ---------------- packed f32x2 helpers ----------------
__device__ __forceinline__ u64 pk2(float lo, float hi) {
    u64 r; asm("mov.b64 %0,{%1,%2};" : "=l"(r) : "f"(lo), "f"(hi)); return r;
}
__device__ __forceinline__ void upk2(u64 v, float& lo, float& hi) {
    asm("mov.b64 {%0,%1},%2;" : "=f"(lo), "=f"(hi) : "l"(v));
}
__device__ __forceinline__ u64 fma2_(u64 a, u64 b, u64 c) {
    u64 d; asm("fma.rn.f32x2 %0,%1,%2,%3;" : "=l"(d) : "l"(a), "l"(b), "l"(c)); return d;
}
__device__ __forceinline__ u64 mul2_(u64 a, u64 b) {
    u64 d; asm("mul.rn.f32x2 %0,%1,%2;" : "=l"(d) : "l"(a), "l"(b)); return d;
}
__device__ __forceinline__ u64 add2_(u64 a, u64 b) {
    u64 d; asm("add.rn.f32x2 %0,%1,%2;" : "=l"(d) : "l"(a), "l"(b)); return d;
}

__device__ __forceinline__ float tanh_a(float u) {
    float th; asm("tanh.approx.f32 %0,%1;" : "=f"(th) : "f"(u)); return th;
}

// Packed tanh-gelu on a pair: 0.5*t*(1+tanh(0.79788456*t + 0.03567741*t^3))
__device__ __forceinline__ u64 gelu2(u64 t, u64 K1, u64 K0, u64 HALF, u64 ONE) {
    u64 tt = mul2_(t, t);
    u64 u  = mul2_(t, fma2_(tt, K1, K0));
    float u0, u1; upk2(u, u0, u1);
    u64 th = pk2(tanh_a(u0), tanh_a(u1));
    return mul2_(mul2_(t, HALF), add2_(th, ONE));
}

// LayerNorm over 10 scalars -> broadcast pairs (n_i, n_i). Affine folded into weights.
__device__ __forceinline__ void ln10(const float* a, u64* nb) {
    float mu = 0.0f;
#pragma unroll
    for (int i = 0; i < 10; i++) mu += a[i];
    mu *= 0.1f;
    float var = 0.0f;
#pragma unroll
    for (int i = 0; i < 10; i++) { float d = a[i] - mu; var = fmaf(d, d, var); }
    var *= 0.1f;
    float r = rsqrtf(var + 1e-5f);
#pragma unroll
    for (int i = 0; i < 10; i++) { float n = (a[i] - mu) * r; nb[i] = pk2(n, n); }
}

// ---------------- one-time weight folding ----------------
// seq-len==1 => softmax(1x1)==1 => attention output == V. So:
//   seq += LN1(seq) @ (diag(g1) Wv Wo) + (b1ln @ (Wv Wo) + bv @ Wo + bo)
//   t    = LN2(seq) @ (diag(g2) W1)    + (b1 + b2ln @ W1)
__global__ void fold_kernel(
    const float* __restrict__ proto,
    const float* __restrict__ Wv, const float* __restrict__ bv,
    const float* __restrict__ Wo, const float* __restrict__ bo,
    const float* __restrict__ g1, const float* __restrict__ b1ln,
    const float* __restrict__ g2, const float* __restrict__ b2ln,
    const float* __restrict__ W1, const float* __restrict__ b1,
    const float* __restrict__ W2, const float* __restrict__ b2,
    const float* __restrict__ Wc, const float* __restrict__ bc)
{
    int t = threadIdx.x;
    for (int i = t; i < NPAR; i += 256) g_par[i] = 0.0f;
    __syncthreads();

    for (int i = t; i < 80; i += 256) g_par[OFF_PROTO + i] = proto[i];
    if (t < 10) {
        float s = 0.0f;
        for (int d = 0; d < 8; d++) s += proto[t * 8 + d] * proto[t * 8 + d];
        g_par[OFF_P2 + t] = s;
    }
#pragma unroll
    for (int l = 0; l < 2; l++) {
        if (t < 100) {
            int i = t / 10, j = t % 10;
            float m = 0.0f;
            for (int k = 0; k < 10; k++) m += Wv[l * 100 + i * 10 + k] * Wo[l * 100 + k * 10 + j];
            g_par[OFF_A + l * 120 + i * 12 + j] = g1[l * 10 + i] * m;
        }
        if (t < 10) {  // folded attention bias, j = t
            float s = bo[l * 10 + t];
            for (int k = 0; k < 10; k++) s += bv[l * 10 + k] * Wo[l * 100 + k * 10 + t];
            for (int i = 0; i < 10; i++) {
                float m = 0.0f;
                for (int k = 0; k < 10; k++) m += Wv[l * 100 + i * 10 + k] * Wo[l * 100 + k * 10 + t];
                s += b1ln[l * 10 + i] * m;
            }
            g_par[OFF_AB + l * 12 + t] = s;
        }
        for (int e = t; e < 640; e += 256) {
            int i = e / 64;
            g_par[OFF_W1 + l * 640 + e] = g2[l * 10 + i] * W1[l * 640 + e];
        }
        if (t < 64) {
            float s = b1[l * 64 + t];
            for (int i = 0; i < 10; i++) s += b2ln[l * 10 + i] * W1[l * 640 + i * 64 + t];
            g_par[OFF_B1 + l * 64 + t] = s;
        }
        for (int e = t; e < 640; e += 256) {
            int f = e / 10, j = e % 10;
            g_par[OFF_W2 + l * 768 + f * 12 + j] = W2[l * 640 + e];
        }
        if (t < 10) g_par[OFF_B2 + l * 12 + t] = b2[l * 10 + t];
    }
    if (t < 10) g_par[OFF_WC + t] = Wc[t];
    if (t == 0) g_par[OFF_BC] = bc[0];
}

// ---------------- main per-sample kernel ----------------
__global__ void __launch_bounds__(256) fwd_kernel(
    const float* __restrict__ x, float* __restrict__ out, int B)
{
    int gid = blockIdx.x * 256 + threadIdx.x;
    if (gid >= B) return;

    const u64 K1   = pk2(0.03567740814f, 0.03567740814f);
    const u64 K0   = pk2(0.7978845608f,  0.7978845608f);
    const u64 HALF = pk2(0.5f, 0.5f);
    const u64 ONE  = pk2(1.0f, 1.0f);

    const float4* xp = reinterpret_cast<const float4*>(x) + gid * 2;
    float4 xa = xp[0], xb = xp[1];
    float x2 = xa.x * xa.x + xa.y * xa.y + xa.z * xa.z + xa.w * xa.w +
               xb.x * xb.x + xb.y * xb.y + xb.z * xb.z + xb.w * xb.w;

    // p2 values into a compile-time-indexed local array (stays in regs)
    float p2a[12];
    {
        float4 q0 = c_par[F4_P2], q1 = c_par[F4_P2 + 1], q2 = c_par[F4_P2 + 2];
        p2a[0] = q0.x; p2a[1] = q0.y; p2a[2]  = q0.z; p2a[3]  = q0.w;
        p2a[4] = q1.x; p2a[5] = q1.y; p2a[6]  = q1.z; p2a[7]  = q1.w;
        p2a[8] = q2.x; p2a[9] = q2.y; p2a[10] = q2.z; p2a[11] = q2.w;
    }

    // RBF features: exp(-|x-p_j|^2) = exp(2 x.p - |x|^2 - |p|^2)
    float s[10];
#pragma unroll
    for (int j = 0; j < 10; j++) {
        float4 p0 = c_par[F4_PROTO + 2 * j];
        float4 p1 = c_par[F4_PROTO + 2 * j + 1];
        float dot = xa.x * p0.x + xa.y * p0.y + xa.z * p0.z + xa.w * p0.w +
                    xb.x * p1.x + xb.y * p1.y + xb.z * p1.z + xb.w * p1.w;
        s[j] = __expf(fmaf(2.0f, dot, -x2 - p2a[j]));
    }

    u64 nb[10];
    u64 acc[5];

#pragma unroll
    for (int l = 0; l < 2; l++) {
        // ---- attention block (collapsed to folded 10x10 matvec) ----
        ln10(s, nb);
        {
            float4 q0 = c_par[F4_AB + l * 3];
            float4 q1 = c_par[F4_AB + l * 3 + 1];
            float4 q2 = c_par[F4_AB + l * 3 + 2];
            acc[0] = pk2(q0.x, q0.y); acc[1] = pk2(q0.z, q0.w);
            acc[2] = pk2(q1.x, q1.y); acc[3] = pk2(q1.z, q1.w);
            acc[4] = pk2(q2.x, q2.y);
        }
#pragma unroll
        for (int i = 0; i < 10; i++) {
            int r = F4_A + l * 30 + i * 3;
            float4 w0 = c_par[r], w1 = c_par[r + 1], w2 = c_par[r + 2];
            acc[0] = fma2_(nb[i], pk2(w0.x, w0.y), acc[0]);
            acc[1] = fma2_(nb[i], pk2(w0.z, w0.w), acc[1]);
            acc[2] = fma2_(nb[i], pk2(w1.x, w1.y), acc[2]);
            acc[3] = fma2_(nb[i], pk2(w1.z, w1.w), acc[3]);
            acc[4] = fma2_(nb[i], pk2(w2.x, w2.y), acc[4]);
        }
#pragma unroll
        for (int p = 0; p < 5; p++) {
            float a0, a1; upk2(acc[p], a0, a1);
            s[2 * p] += a0; s[2 * p + 1] += a1;
        }

        // ---- FFN block ----
        ln10(s, nb);
        {
            float4 q0 = c_par[F4_B2 + l * 3];
            float4 q1 = c_par[F4_B2 + l * 3 + 1];
            float4 q2 = c_par[F4_B2 + l * 3 + 2];
            acc[0] = pk2(q0.x, q0.y); acc[1] = pk2(q0.z, q0.w);
            acc[2] = pk2(q1.x, q1.y); acc[3] = pk2(q1.z, q1.w);
            acc[4] = pk2(q2.x, q2.y);
        }
#pragma unroll 1
        for (int f = 0; f < 64; f += 4) {
            float4 bq = c_par[F4_B1 + l * 16 + (f >> 2)];
            u64 t01 = pk2(bq.x, bq.y);
            u64 t23 = pk2(bq.z, bq.w);
#pragma unroll
            for (int i = 0; i < 10; i++) {
                float4 w = c_par[F4_W1 + l * 160 + i * 16 + (f >> 2)];
                t01 = fma2_(nb[i], pk2(w.x, w.y), t01);
                t23 = fma2_(nb[i], pk2(w.z, w.w), t23);
            }
            u64 g01 = gelu2(t01, K1, K0, HALF, ONE);
            u64 g23 = gelu2(t23, K1, K0, HALF, ONE);
            float g0, g1, g2, g3;
            upk2(g01, g0, g1); upk2(g23, g2, g3);
            float gl[4] = {g0, g1, g2, g3};
#pragma unroll
            for (int fi = 0; fi < 4; fi++) {
                u64 gg = pk2(gl[fi], gl[fi]);
                int r = F4_W2 + l * 192 + (f + fi) * 3;
                float4 w0 = c_par[r], w1 = c_par[r + 1], w2 = c_par[r + 2];
                acc[0] = fma2_(gg, pk2(w0.x, w0.y), acc[0]);
                acc[1] = fma2_(gg, pk2(w0.z, w0.w), acc[1]);
                acc[2] = fma2_(gg, pk2(w1.x, w1.y), acc[2]);
                acc[3] = fma2_(gg, pk2(w1.z, w1.w), acc[3]);
                acc[4] = fma2_(gg, pk2(w2.x, w2.y), acc[4]);
            }
        }
#pragma unroll
        for (int p = 0; p < 5; p++) {
            float a0, a1; upk2(acc[p], a0, a1);
            s[2 * p] += a0; s[2 * p + 1] += a1;
        }
    }

    // classifier
    float wca[12];
    {
        float4 q0 = c_par[F4_WC], q1 = c_par[F4_WC + 1], q2 = c_par[F4_WC + 2];
        wca[0] = q0.x; wca[1] = q0.y; wca[2]  = q0.z; wca[3]  = q0.w;
        wca[4] = q1.x; wca[5] = q1.y; wca[6]  = q1.z; wca[7]  = q1.w;
        wca[8] = q2.x; wca[9] = q2.y; wca[10] = q2.z; wca[11] = q2.w;
    }
    float logit = c_par[F4_BC].x;
#pragma unroll
    for (int j = 0; j < 10; j++) logit = fmaf(s[j], wca[j], logit);
    out[gid] = 1.0f / (1.0f + __expf(-logit));
}

// ---------------- launch ----------------
extern "C" void kernel_launch(void* const* d_in, const int* in_sizes, int n_in,
                              void* d_out, int out_size)
{
    const float* x = (const float*)d_in[0];
    int B = in_sizes[0] / 8;

    // input order: x, prototypes, Wq, bq, Wk, bk, Wv, bv, Wo, bo,
    //              ln1_g, ln1_b, ln2_g, ln2_b, W1, b1, W2, b2, Wc, bc
    fold_kernel<<<1, 256>>>(
        (const float*)d_in[1],                           // prototypes
        (const float*)d_in[6],  (const float*)d_in[7],   // Wv, bv
        (const float*)d_in[8],  (const float*)d_in[9],   // Wo, bo
        (const float*)d_in[10], (const float*)d_in[11],  // ln1_g, ln1_b
        (const float*)d_in[12], (const float*)d_in[13],  // ln2_g, ln2_b
        (const float*)d_in[14], (const float*)d_in[15],  // W1, b1
        (const float*)d_in[16], (const float*)d_in[17],  // W2, b2
        (const float*)d_in[18], (const float*)d_in[19]); // Wc, bc

    // stage folded params onto the constant port (graph-capturable D2D copy)
    void* csym = nullptr; void* gsym = nullptr;
    cudaGetSymbolAddress(&csym, c_par);
    cudaGetSymbolAddress(&gsym, g_par);
    cudaMemcpyAsync(csym, gsym, NPAR * sizeof(float), cudaMemcpyDeviceToDevice);

    fwd_kernel<<<(B + 255) / 256, 256>>>(x, (float*)d_out, B);
}

// round 4
// speedup vs baseline: 1.8523x; 1.8523x over previous
#include <cuda_runtime.h>
#include <cstdint>

typedef unsigned long long u64;

// ---------------- folded-parameter block layout (floats) ----------------
#define OFF_PROTO 0      // 10 x 8
#define OFF_P2    80     // 10 (+2 pad)
#define OFF_A     96     // 2 x 10 x 12 (row-padded 10->12): diag(ln1_g) @ Wv @ Wo
#define OFF_AB    336    // 2 x 12: folded attention bias
#define OFF_W1    360    // 2 x 10 x 64: diag(ln2_g) @ W1
#define OFF_B1    1640   // 2 x 64: b1 + ln2_b @ W1
#define OFF_W2    1768   // 2 x 64 x 12 (row-padded 10->12)
#define OFF_B2    3304   // 2 x 12
#define OFF_WC    3328   // 12
#define OFF_BC    3340   // 1
#define NPAR      3344

__device__ float g_par[NPAR];

// ---------------- packed f32x2 helpers ----------------
__device__ __forceinline__ u64 pk2(float lo, float hi) {
    u64 r; asm("mov.b64 %0,{%1,%2};" : "=l"(r) : "f"(lo), "f"(hi)); return r;
}
__device__ __forceinline__ void upk2(u64 v, float& lo, float& hi) {
    asm("mov.b64 {%0,%1},%2;" : "=f"(lo), "=f"(hi) : "l"(v));
}
__device__ __forceinline__ u64 fma2_(u64 a, u64 b, u64 c) {
    u64 d; asm("fma.rn.f32x2 %0,%1,%2,%3;" : "=l"(d) : "l"(a), "l"(b), "l"(c)); return d;
}
__device__ __forceinline__ u64 mul2_(u64 a, u64 b) {
    u64 d; asm("mul.rn.f32x2 %0,%1,%2;" : "=l"(d) : "l"(a), "l"(b)); return d;
}
__device__ __forceinline__ u64 add2_(u64 a, u64 b) {
    u64 d; asm("add.rn.f32x2 %0,%1,%2;" : "=l"(d) : "l"(a), "l"(b)); return d;
}
__device__ __forceinline__ float tanh_a(float u) {
    float th; asm("tanh.approx.f32 %0,%1;" : "=f"(th) : "f"(u)); return th;
}

// Packed tanh-gelu on a pair: 0.5*t*(1+tanh(0.79788456*t + 0.03567741*t^3))
__device__ __forceinline__ u64 gelu2(u64 t) {
    const u64 K1   = pk2(0.03567740814f, 0.03567740814f);
    const u64 K0   = pk2(0.7978845608f,  0.7978845608f);
    const u64 HALF = pk2(0.5f, 0.5f);
    const u64 ONE  = pk2(1.0f, 1.0f);
    u64 tt = mul2_(t, t);
    u64 u  = mul2_(t, fma2_(tt, K1, K0));
    float u0, u1; upk2(u, u0, u1);
    u64 th = pk2(tanh_a(u0), tanh_a(u1));
    return mul2_(mul2_(t, HALF), add2_(th, ONE));
}

// LayerNorm over 10 scalars -> broadcast pairs. Affine folded into weights.
__device__ __forceinline__ void ln10(const float* a, u64* nb) {
    float mu = 0.0f;
#pragma unroll
    for (int i = 0; i < 10; i++) mu += a[i];
    mu *= 0.1f;
    float var = 0.0f;
#pragma unroll
    for (int i = 0; i < 10; i++) { float d = a[i] - mu; var = fmaf(d, d, var); }
    var *= 0.1f;
    float r = rsqrtf(var + 1e-5f);
#pragma unroll
    for (int i = 0; i < 10; i++) { float n = (a[i] - mu) * r; nb[i] = pk2(n, n); }
}

// ---------------- one-time weight folding ----------------
// seq-len==1 => softmax(1x1)==1 => attention output == V. So:
//   seq += LN1(seq) @ (diag(g1) Wv Wo) + (b1ln @ (Wv Wo) + bv @ Wo + bo)
//   t    = LN2(seq) @ (diag(g2) W1)    + (b1 + b2ln @ W1)
__global__ void fold_kernel(
    const float* __restrict__ proto,
    const float* __restrict__ Wv, const float* __restrict__ bv,
    const float* __restrict__ Wo, const float* __restrict__ bo,
    const float* __restrict__ g1, const float* __restrict__ b1ln,
    const float* __restrict__ g2, const float* __restrict__ b2ln,
    const float* __restrict__ W1, const float* __restrict__ b1,
    const float* __restrict__ W2, const float* __restrict__ b2,
    const float* __restrict__ Wc, const float* __restrict__ bc)
{
    int t = threadIdx.x;
    for (int i = t; i < NPAR; i += 256) g_par[i] = 0.0f;
    __syncthreads();

    for (int i = t; i < 80; i += 256) g_par[OFF_PROTO + i] = proto[i];
    if (t < 10) {
        float s = 0.0f;
        for (int d = 0; d < 8; d++) s += proto[t * 8 + d] * proto[t * 8 + d];
        g_par[OFF_P2 + t] = s;
    }
#pragma unroll
    for (int l = 0; l < 2; l++) {
        if (t < 100) {
            int i = t / 10, j = t % 10;
            float m = 0.0f;
            for (int k = 0; k < 10; k++) m += Wv[l * 100 + i * 10 + k] * Wo[l * 100 + k * 10 + j];
            g_par[OFF_A + l * 120 + i * 12 + j] = g1[l * 10 + i] * m;
        }
        if (t < 10) {  // folded attention bias, j = t
            float s = bo[l * 10 + t];
            for (int k = 0; k < 10; k++) s += bv[l * 10 + k] * Wo[l * 100 + k * 10 + t];
            for (int i = 0; i < 10; i++) {
                float m = 0.0f;
                for (int k = 0; k < 10; k++) m += Wv[l * 100 + i * 10 + k] * Wo[l * 100 + k * 10 + t];
                s += b1ln[l * 10 + i] * m;
            }
            g_par[OFF_AB + l * 12 + t] = s;
        }
        for (int e = t; e < 640; e += 256) {
            int i = e / 64;
            g_par[OFF_W1 + l * 640 + e] = g2[l * 10 + i] * W1[l * 640 + e];
        }
        if (t < 64) {
            float s = b1[l * 64 + t];
            for (int i = 0; i < 10; i++) s += b2ln[l * 10 + i] * W1[l * 640 + i * 64 + t];
            g_par[OFF_B1 + l * 64 + t] = s;
        }
        for (int e = t; e < 640; e += 256) {
            int f = e / 10, j = e % 10;
            g_par[OFF_W2 + l * 768 + f * 12 + j] = W2[l * 640 + e];
        }
        if (t < 10) g_par[OFF_B2 + l * 12 + t] = b2[l * 10 + t];
    }
    if (t < 10) g_par[OFF_WC + t] = Wc[t];
    if (t == 0) g_par[OFF_BC] = bc[0];
}

// ---------------- main kernel: 2 samples per thread ----------------
__global__ void __launch_bounds__(256) fwd_kernel(
    const float* __restrict__ x, float* __restrict__ out, int B)
{
    __shared__ __align__(16) float sm[NPAR];
    for (int i = threadIdx.x; i < NPAR; i += 256) sm[i] = g_par[i];
    __syncthreads();

    int pid = blockIdx.x * 256 + threadIdx.x;   // pair id
    int i0 = pid * 2;
    if (i0 >= B) return;
    bool haveB = (i0 + 1 < B);

    // load both samples (64B contiguous)
    const float4* xp = reinterpret_cast<const float4*>(x) + (u64)i0 * 2;
    float4 xa0 = xp[0], xb0 = xp[1];
    float4 xa1 = haveB ? xp[2] : xa0;
    float4 xb1 = haveB ? xp[3] : xb0;

    float x2A = xa0.x*xa0.x + xa0.y*xa0.y + xa0.z*xa0.z + xa0.w*xa0.w +
                xb0.x*xb0.x + xb0.y*xb0.y + xb0.z*xb0.z + xb0.w*xb0.w;
    float x2B = xa1.x*xa1.x + xa1.y*xa1.y + xa1.z*xa1.z + xa1.w*xa1.w +
                xb1.x*xb1.x + xb1.y*xb1.y + xb1.z*xb1.z + xb1.w*xb1.w;

    // RBF features: exp(-|x-p_j|^2) = exp(2 x.p - |x|^2 - |p|^2)
    float sA[10], sB[10];
#pragma unroll
    for (int j = 0; j < 10; j++) {
        const float4* pr = reinterpret_cast<const float4*>(&sm[OFF_PROTO + j * 8]);
        float4 p0 = pr[0], p1 = pr[1];
        float p2 = sm[OFF_P2 + j];
        float dA = xa0.x*p0.x + xa0.y*p0.y + xa0.z*p0.z + xa0.w*p0.w +
                   xb0.x*p1.x + xb0.y*p1.y + xb0.z*p1.z + xb0.w*p1.w;
        float dB = xa1.x*p0.x + xa1.y*p0.y + xa1.z*p0.z + xa1.w*p0.w +
                   xb1.x*p1.x + xb1.y*p1.y + xb1.z*p1.z + xb1.w*p1.w;
        sA[j] = __expf(fmaf(2.0f, dA, -x2A - p2));
        sB[j] = __expf(fmaf(2.0f, dB, -x2B - p2));
    }

    u64 nbA[10], nbB[10];
    u64 accA[5], accB[5];

#pragma unroll
    for (int l = 0; l < 2; l++) {
        const float* A  = &sm[OFF_A  + l * 120];
        const float* aB = &sm[OFF_AB + l * 12];
        const float* W1 = &sm[OFF_W1 + l * 640];
        const float* b1 = &sm[OFF_B1 + l * 64];
        const float* W2 = &sm[OFF_W2 + l * 768];
        const float* b2 = &sm[OFF_B2 + l * 12];

        // ---- attention block (collapsed to folded 10x10 matvec) ----
        ln10(sA, nbA);
        ln10(sB, nbB);
#pragma unroll
        for (int p = 0; p < 5; p++) {
            u64 b = *reinterpret_cast<const u64*>(&aB[2 * p]);
            accA[p] = b; accB[p] = b;
        }
#pragma unroll
        for (int i = 0; i < 10; i++) {
            const ulonglong2* ar = reinterpret_cast<const ulonglong2*>(&A[i * 12]);
            ulonglong2 a01 = ar[0];
            ulonglong2 a23 = ar[1];
            u64 a4 = *reinterpret_cast<const u64*>(&A[i * 12 + 8]);
            accA[0] = fma2_(nbA[i], a01.x, accA[0]);  accB[0] = fma2_(nbB[i], a01.x, accB[0]);
            accA[1] = fma2_(nbA[i], a01.y, accA[1]);  accB[1] = fma2_(nbB[i], a01.y, accB[1]);
            accA[2] = fma2_(nbA[i], a23.x, accA[2]);  accB[2] = fma2_(nbB[i], a23.x, accB[2]);
            accA[3] = fma2_(nbA[i], a23.y, accA[3]);  accB[3] = fma2_(nbB[i], a23.y, accB[3]);
            accA[4] = fma2_(nbA[i], a4,    accA[4]);  accB[4] = fma2_(nbB[i], a4,    accB[4]);
        }
#pragma unroll
        for (int p = 0; p < 5; p++) {
            float a0, a1; upk2(accA[p], a0, a1);
            sA[2 * p] += a0; sA[2 * p + 1] += a1;
            upk2(accB[p], a0, a1);
            sB[2 * p] += a0; sB[2 * p + 1] += a1;
        }

        // ---- FFN block ----
        ln10(sA, nbA);
        ln10(sB, nbB);
#pragma unroll
        for (int p = 0; p < 5; p++) {
            u64 b = *reinterpret_cast<const u64*>(&b2[2 * p]);
            accA[p] = b; accB[p] = b;
        }
#pragma unroll 1
        for (int f = 0; f < 64; f += 4) {
            u64 bb01 = *reinterpret_cast<const u64*>(&b1[f]);
            u64 bb23 = *reinterpret_cast<const u64*>(&b1[f + 2]);
            u64 tA01 = bb01, tA23 = bb23, tB01 = bb01, tB23 = bb23;
#pragma unroll
            for (int i = 0; i < 10; i++) {
                ulonglong2 w = *reinterpret_cast<const ulonglong2*>(&W1[i * 64 + f]);
                tA01 = fma2_(nbA[i], w.x, tA01);  tB01 = fma2_(nbB[i], w.x, tB01);
                tA23 = fma2_(nbA[i], w.y, tA23);  tB23 = fma2_(nbB[i], w.y, tB23);
            }
            u64 gA01 = gelu2(tA01), gA23 = gelu2(tA23);
            u64 gB01 = gelu2(tB01), gB23 = gelu2(tB23);
            float gA[4], gB[4];
            upk2(gA01, gA[0], gA[1]); upk2(gA23, gA[2], gA[3]);
            upk2(gB01, gB[0], gB[1]); upk2(gB23, gB[2], gB[3]);
#pragma unroll
            for (int fi = 0; fi < 4; fi++) {
                u64 ggA = pk2(gA[fi], gA[fi]);
                u64 ggB = pk2(gB[fi], gB[fi]);
                const ulonglong2* wr = reinterpret_cast<const ulonglong2*>(&W2[(f + fi) * 12]);
                ulonglong2 w01 = wr[0];
                ulonglong2 w23 = wr[1];
                u64 w4 = *reinterpret_cast<const u64*>(&W2[(f + fi) * 12 + 8]);
                accA[0] = fma2_(ggA, w01.x, accA[0]);  accB[0] = fma2_(ggB, w01.x, accB[0]);
                accA[1] = fma2_(ggA, w01.y, accA[1]);  accB[1] = fma2_(ggB, w01.y, accB[1]);
                accA[2] = fma2_(ggA, w23.x, accA[2]);  accB[2] = fma2_(ggB, w23.x, accB[2]);
                accA[3] = fma2_(ggA, w23.y, accA[3]);  accB[3] = fma2_(ggB, w23.y, accB[3]);
                accA[4] = fma2_(ggA, w4,    accA[4]);  accB[4] = fma2_(ggB, w4,    accB[4]);
            }
        }
#pragma unroll
        for (int p = 0; p < 5; p++) {
            float a0, a1; upk2(accA[p], a0, a1);
            sA[2 * p] += a0; sA[2 * p + 1] += a1;
            upk2(accB[p], a0, a1);
            sB[2 * p] += a0; sB[2 * p + 1] += a1;
        }
    }

    // classifier + sigmoid
    float lA = sm[OFF_BC], lB = sm[OFF_BC];
#pragma unroll
    for (int j = 0; j < 10; j++) {
        float w = sm[OFF_WC + j];
        lA = fmaf(sA[j], w, lA);
        lB = fmaf(sB[j], w, lB);
    }
    float oA = 1.0f / (1.0f + __expf(-lA));
    float oB = 1.0f / (1.0f + __expf(-lB));
    if (haveB) {
        *reinterpret_cast<float2*>(out + i0) = make_float2(oA, oB);
    } else {
        out[i0] = oA;
    }
}

// ---------------- launch ----------------
extern "C" void kernel_launch(void* const* d_in, const int* in_sizes, int n_in,
                              void* d_out, int out_size)
{
    const float* x = (const float*)d_in[0];
    int B = in_sizes[0] / 8;

    // input order: x, prototypes, Wq, bq, Wk, bk, Wv, bv, Wo, bo,
    //              ln1_g, ln1_b, ln2_g, ln2_b, W1, b1, W2, b2, Wc, bc
    fold_kernel<<<1, 256>>>(
        (const float*)d_in[1],                           // prototypes
        (const float*)d_in[6],  (const float*)d_in[7],   // Wv, bv
        (const float*)d_in[8],  (const float*)d_in[9],   // Wo, bo
        (const float*)d_in[10], (const float*)d_in[11],  // ln1_g, ln1_b
        (const float*)d_in[12], (const float*)d_in[13],  // ln2_g, ln2_b
        (const float*)d_in[14], (const float*)d_in[15],  // W1, b1
        (const float*)d_in[16], (const float*)d_in[17],  // W2, b2
        (const float*)d_in[18], (const float*)d_in[19]); // Wc, bc

    int pairs = (B + 1) / 2;
    fwd_kernel<<<(pairs + 255) / 256, 256>>>(x, (float*)d_out, B);
}

// round 5
// speedup vs baseline: 1.8682x; 1.0086x over previous
#include <cuda_runtime.h>
#include <cstdint>

typedef unsigned long long u64;

// ---------------- folded-parameter block layout (floats) ----------------
#define OFF_PROTO 0      // 10 x 8
#define OFF_P2    80     // 10 (+2 pad)
#define OFF_A     96     // 2 x 10 x 12 (row-padded 10->12): diag(ln1_g) @ Wv @ Wo
#define OFF_AB    336    // 2 x 12: folded attention bias
#define OFF_W1    360    // 2 x 10 x 64: diag(ln2_g) @ W1
#define OFF_B1    1640   // 2 x 64: b1 + ln2_b @ W1
#define OFF_W2    1768   // 2 x 64 x 12 (row-padded 10->12)
#define OFF_B2    3304   // 2 x 12
#define OFF_WC    3328   // 12
#define OFF_BC    3340   // 1
// duplicated-pair section (for sample-packed math)
#define OFF_PD    3344   // 10 x 8 x 2: prototypes as (p,p) pairs
#define OFF_P2D   3504   // 10 x 2: NEGATED |p|^2 as pairs
#define OFF_WCD   3524   // 10 x 2: Wc as pairs
#define NPAR      3544

__device__ float g_par[NPAR];

// ---------------- packed f32x2 helpers ----------------
__device__ __forceinline__ u64 pk2(float lo, float hi) {
    u64 r; asm("mov.b64 %0,{%1,%2};" : "=l"(r) : "f"(lo), "f"(hi)); return r;
}
__device__ __forceinline__ void upk2(u64 v, float& lo, float& hi) {
    asm("mov.b64 {%0,%1},%2;" : "=f"(lo), "=f"(hi) : "l"(v));
}
__device__ __forceinline__ u64 fma2_(u64 a, u64 b, u64 c) {
    u64 d; asm("fma.rn.f32x2 %0,%1,%2,%3;" : "=l"(d) : "l"(a), "l"(b), "l"(c)); return d;
}
__device__ __forceinline__ u64 mul2_(u64 a, u64 b) {
    u64 d; asm("mul.rn.f32x2 %0,%1,%2;" : "=l"(d) : "l"(a), "l"(b)); return d;
}
__device__ __forceinline__ u64 add2_(u64 a, u64 b) {
    u64 d; asm("add.rn.f32x2 %0,%1,%2;" : "=l"(d) : "l"(a), "l"(b)); return d;
}
__device__ __forceinline__ float tanh_a(float u) {
    float th; asm("tanh.approx.f32 %0,%1;" : "=f"(th) : "f"(u)); return th;
}

// Packed tanh-gelu, 5 fma-pipe ops + 2 MUFU:
// gelu(t) = ht + ht*tanh(u), ht = 0.5t, u = t*(K0 + K1*t^2)
__device__ __forceinline__ u64 gelu2(u64 t) {
    const u64 K1   = pk2(0.03567740814f, 0.03567740814f);
    const u64 K0   = pk2(0.7978845608f,  0.7978845608f);
    const u64 HALF = pk2(0.5f, 0.5f);
    u64 tt = mul2_(t, t);
    u64 in = fma2_(tt, K1, K0);
    u64 u  = mul2_(t, in);
    float u0, u1; upk2(u, u0, u1);
    u64 th = pk2(tanh_a(u0), tanh_a(u1));
    u64 ht = mul2_(t, HALF);
    return fma2_(ht, th, ht);
}

// Sample-packed LayerNorm over 10 features: sP[j] = (sA_j, sB_j) -> nP[j] packed.
// LN reduces over j; samples independent -> fully elementwise-packed, no horizontal ops.
__device__ __forceinline__ void ln10p(const u64* sP, u64* nP) {
    const u64 TENTH = pk2(0.1f, 0.1f);
    const u64 NEG1  = pk2(-1.0f, -1.0f);
    u64 m01 = add2_(sP[0], sP[1]);
    u64 m23 = add2_(sP[2], sP[3]);
    u64 m45 = add2_(sP[4], sP[5]);
    u64 m67 = add2_(sP[6], sP[7]);
    u64 m89 = add2_(sP[8], sP[9]);
    u64 mu = add2_(add2_(add2_(m01, m23), add2_(m45, m67)), m89);
    mu = mul2_(mu, TENTH);
    u64 nmu = mul2_(mu, NEG1);
    u64 d[10];
#pragma unroll
    for (int j = 0; j < 10; j++) d[j] = add2_(sP[j], nmu);
    u64 v = mul2_(d[0], d[0]);
#pragma unroll
    for (int j = 1; j < 10; j++) v = fma2_(d[j], d[j], v);
    v = mul2_(v, TENTH);
    float vA, vB; upk2(v, vA, vB);
    u64 rp = pk2(rsqrtf(vA + 1e-5f), rsqrtf(vB + 1e-5f));
#pragma unroll
    for (int j = 0; j < 10; j++) nP[j] = mul2_(d[j], rp);
}

// ---------------- one-time weight folding ----------------
// seq-len==1 => softmax(1x1)==1 => attention output == V. So:
//   seq += LN1(seq) @ (diag(g1) Wv Wo) + (b1ln @ (Wv Wo) + bv @ Wo + bo)
//   t    = LN2(seq) @ (diag(g2) W1)    + (b1 + b2ln @ W1)
__global__ void fold_kernel(
    const float* __restrict__ proto,
    const float* __restrict__ Wv, const float* __restrict__ bv,
    const float* __restrict__ Wo, const float* __restrict__ bo,
    const float* __restrict__ g1, const float* __restrict__ b1ln,
    const float* __restrict__ g2, const float* __restrict__ b2ln,
    const float* __restrict__ W1, const float* __restrict__ b1,
    const float* __restrict__ W2, const float* __restrict__ b2,
    const float* __restrict__ Wc, const float* __restrict__ bc)
{
    int t = threadIdx.x;
    for (int i = t; i < NPAR; i += 256) g_par[i] = 0.0f;
    __syncthreads();

    for (int i = t; i < 80; i += 256) {
        float v = proto[i];
        g_par[OFF_PROTO + i] = v;
        g_par[OFF_PD + 2 * i] = v;
        g_par[OFF_PD + 2 * i + 1] = v;
    }
    if (t < 10) {
        float s = 0.0f;
        for (int d = 0; d < 8; d++) s += proto[t * 8 + d] * proto[t * 8 + d];
        g_par[OFF_P2 + t] = s;
        g_par[OFF_P2D + 2 * t] = -s;       // stored negated
        g_par[OFF_P2D + 2 * t + 1] = -s;
    }
#pragma unroll
    for (int l = 0; l < 2; l++) {
        if (t < 100) {
            int i = t / 10, j = t % 10;
            float m = 0.0f;
            for (int k = 0; k < 10; k++) m += Wv[l * 100 + i * 10 + k] * Wo[l * 100 + k * 10 + j];
            g_par[OFF_A + l * 120 + i * 12 + j] = g1[l * 10 + i] * m;
        }
        if (t < 10) {  // folded attention bias, j = t
            float s = bo[l * 10 + t];
            for (int k = 0; k < 10; k++) s += bv[l * 10 + k] * Wo[l * 100 + k * 10 + t];
            for (int i = 0; i < 10; i++) {
                float m = 0.0f;
                for (int k = 0; k < 10; k++) m += Wv[l * 100 + i * 10 + k] * Wo[l * 100 + k * 10 + t];
                s += b1ln[l * 10 + i] * m;
            }
            g_par[OFF_AB + l * 12 + t] = s;
        }
        for (int e = t; e < 640; e += 256) {
            int i = e / 64;
            g_par[OFF_W1 + l * 640 + e] = g2[l * 10 + i] * W1[l * 640 + e];
        }
        if (t < 64) {
            float s = b1[l * 64 + t];
            for (int i = 0; i < 10; i++) s += b2ln[l * 10 + i] * W1[l * 640 + i * 64 + t];
            g_par[OFF_B1 + l * 64 + t] = s;
        }
        for (int e = t; e < 640; e += 256) {
            int f = e / 10, j = e % 10;
            g_par[OFF_W2 + l * 768 + f * 12 + j] = W2[l * 640 + e];
        }
        if (t < 10) g_par[OFF_B2 + l * 12 + t] = b2[l * 10 + t];
    }
    if (t < 10) {
        float w = Wc[t];
        g_par[OFF_WC + t] = w;
        g_par[OFF_WCD + 2 * t] = w;
        g_par[OFF_WCD + 2 * t + 1] = w;
    }
    if (t == 0) g_par[OFF_BC] = bc[0];
}

// ---------------- main kernel: 2 samples per thread, sample-packed state ----------------
__global__ void __launch_bounds__(256) fwd_kernel(
    const float* __restrict__ x, float* __restrict__ out, int B)
{
    __shared__ __align__(16) float sm[NPAR];
    for (int i = threadIdx.x; i < NPAR; i += 256) sm[i] = g_par[i];
    __syncthreads();

    int pid = blockIdx.x * 256 + threadIdx.x;   // pair id
    int i0 = pid * 2;
    if (i0 >= B) return;
    bool haveB = (i0 + 1 < B);

    // load both samples (64B contiguous)
    const float4* xp = reinterpret_cast<const float4*>(x) + (u64)i0 * 2;
    float4 xa0 = xp[0], xb0 = xp[1];
    float4 xa1 = haveB ? xp[2] : xa0;
    float4 xb1 = haveB ? xp[3] : xb0;

    const u64 TWO  = pk2(2.0f, 2.0f);
    const u64 NEG1 = pk2(-1.0f, -1.0f);

    // sample-packed input components
    u64 X[8];
    X[0] = pk2(xa0.x, xa1.x); X[1] = pk2(xa0.y, xa1.y);
    X[2] = pk2(xa0.z, xa1.z); X[3] = pk2(xa0.w, xa1.w);
    X[4] = pk2(xb0.x, xb1.x); X[5] = pk2(xb0.y, xb1.y);
    X[6] = pk2(xb0.z, xb1.z); X[7] = pk2(xb0.w, xb1.w);

    u64 x2p = mul2_(X[0], X[0]);
#pragma unroll
    for (int c = 1; c < 8; c++) x2p = fma2_(X[c], X[c], x2p);
    u64 nx2p = mul2_(x2p, NEG1);

    // RBF features, packed: exp(2 x.p - |x|^2 - |p|^2). sP[j] = (sA_j, sB_j)
    u64 sP[10];
#pragma unroll
    for (int j = 0; j < 10; j++) {
        const u64* pd = reinterpret_cast<const u64*>(&sm[OFF_PD + j * 16]);
        u64 dp = mul2_(X[0], pd[0]);
#pragma unroll
        for (int c = 1; c < 8; c++) dp = fma2_(X[c], pd[c], dp);
        u64 np2 = *reinterpret_cast<const u64*>(&sm[OFF_P2D + 2 * j]); // -|p|^2 pair
        u64 arg = fma2_(TWO, dp, add2_(nx2p, np2));
        float a0, a1; upk2(arg, a0, a1);
        sP[j] = pk2(__expf(a0), __expf(a1));
    }

    u64 nP[10], nbA[10], nbB[10];
    u64 accA[5], accB[5];

#pragma unroll
    for (int l = 0; l < 2; l++) {
        const float* A  = &sm[OFF_A  + l * 120];
        const float* aB = &sm[OFF_AB + l * 12];
        const float* W1 = &sm[OFF_W1 + l * 640];
        const float* b1 = &sm[OFF_B1 + l * 64];
        const float* W2 = &sm[OFF_W2 + l * 768];
        const float* b2 = &sm[OFF_B2 + l * 12];

        // ---- attention block (collapsed to folded 10x10 matvec) ----
        ln10p(sP, nP);
#pragma unroll
        for (int i = 0; i < 10; i++) {
            float lo, hi; upk2(nP[i], lo, hi);
            nbA[i] = pk2(lo, lo); nbB[i] = pk2(hi, hi);
        }
#pragma unroll
        for (int p = 0; p < 5; p++) {
            u64 b = *reinterpret_cast<const u64*>(&aB[2 * p]);
            accA[p] = b; accB[p] = b;
        }
#pragma unroll
        for (int i = 0; i < 10; i++) {
            const ulonglong2* ar = reinterpret_cast<const ulonglong2*>(&A[i * 12]);
            ulonglong2 a01 = ar[0];
            ulonglong2 a23 = ar[1];
            u64 a4 = *reinterpret_cast<const u64*>(&A[i * 12 + 8]);
            accA[0] = fma2_(nbA[i], a01.x, accA[0]);  accB[0] = fma2_(nbB[i], a01.x, accB[0]);
            accA[1] = fma2_(nbA[i], a01.y, accA[1]);  accB[1] = fma2_(nbB[i], a01.y, accB[1]);
            accA[2] = fma2_(nbA[i], a23.x, accA[2]);  accB[2] = fma2_(nbB[i], a23.x, accB[2]);
            accA[3] = fma2_(nbA[i], a23.y, accA[3]);  accB[3] = fma2_(nbB[i], a23.y, accB[3]);
            accA[4] = fma2_(nbA[i], a4,    accA[4]);  accB[4] = fma2_(nbB[i], a4,    accB[4]);
        }
        // packed residual: repack output-packed accs into sample-packed pairs
#pragma unroll
        for (int p = 0; p < 5; p++) {
            float a0, a1, b0, b1v;
            upk2(accA[p], a0, a1); upk2(accB[p], b0, b1v);
            sP[2 * p]     = add2_(sP[2 * p],     pk2(a0, b0));
            sP[2 * p + 1] = add2_(sP[2 * p + 1], pk2(a1, b1v));
        }

        // ---- FFN block ----
        ln10p(sP, nP);
#pragma unroll
        for (int i = 0; i < 10; i++) {
            float lo, hi; upk2(nP[i], lo, hi);
            nbA[i] = pk2(lo, lo); nbB[i] = pk2(hi, hi);
        }
#pragma unroll
        for (int p = 0; p < 5; p++) {
            u64 b = *reinterpret_cast<const u64*>(&b2[2 * p]);
            accA[p] = b; accB[p] = b;
        }
#pragma unroll 1
        for (int f = 0; f < 64; f += 4) {
            u64 bb01 = *reinterpret_cast<const u64*>(&b1[f]);
            u64 bb23 = *reinterpret_cast<const u64*>(&b1[f + 2]);
            u64 tA01 = bb01, tA23 = bb23, tB01 = bb01, tB23 = bb23;
#pragma unroll
            for (int i = 0; i < 10; i++) {
                ulonglong2 w = *reinterpret_cast<const ulonglong2*>(&W1[i * 64 + f]);
                tA01 = fma2_(nbA[i], w.x, tA01);  tB01 = fma2_(nbB[i], w.x, tB01);
                tA23 = fma2_(nbA[i], w.y, tA23);  tB23 = fma2_(nbB[i], w.y, tB23);
            }
            u64 gA01 = gelu2(tA01), gA23 = gelu2(tA23);
            u64 gB01 = gelu2(tB01), gB23 = gelu2(tB23);
            float gA[4], gB[4];
            upk2(gA01, gA[0], gA[1]); upk2(gA23, gA[2], gA[3]);
            upk2(gB01, gB[0], gB[1]); upk2(gB23, gB[2], gB[3]);
#pragma unroll
            for (int fi = 0; fi < 4; fi++) {
                u64 ggA = pk2(gA[fi], gA[fi]);
                u64 ggB = pk2(gB[fi], gB[fi]);
                const ulonglong2* wr = reinterpret_cast<const ulonglong2*>(&W2[(f + fi) * 12]);
                ulonglong2 w01 = wr[0];
                ulonglong2 w23 = wr[1];
                u64 w4 = *reinterpret_cast<const u64*>(&W2[(f + fi) * 12 + 8]);
                accA[0] = fma2_(ggA, w01.x, accA[0]);  accB[0] = fma2_(ggB, w01.x, accB[0]);
                accA[1] = fma2_(ggA, w01.y, accA[1]);  accB[1] = fma2_(ggB, w01.y, accB[1]);
                accA[2] = fma2_(ggA, w23.x, accA[2]);  accB[2] = fma2_(ggB, w23.x, accB[2]);
                accA[3] = fma2_(ggA, w23.y, accA[3]);  accB[3] = fma2_(ggB, w23.y, accB[3]);
                accA[4] = fma2_(ggA, w4,    accA[4]);  accB[4] = fma2_(ggB, w4,    accB[4]);
            }
        }
#pragma unroll
        for (int p = 0; p < 5; p++) {
            float a0, a1, b0, b1v;
            upk2(accA[p], a0, a1); upk2(accB[p], b0, b1v);
            sP[2 * p]     = add2_(sP[2 * p],     pk2(a0, b0));
            sP[2 * p + 1] = add2_(sP[2 * p + 1], pk2(a1, b1v));
        }
    }

    // packed classifier + sigmoid
    float bcv = sm[OFF_BC];
    u64 lp = pk2(bcv, bcv);
#pragma unroll
    for (int j = 0; j < 10; j++) {
        u64 wc = *reinterpret_cast<const u64*>(&sm[OFF_WCD + 2 * j]);
        lp = fma2_(sP[j], wc, lp);
    }
    float lA, lB; upk2(lp, lA, lB);
    float oA = 1.0f / (1.0f + __expf(-lA));
    float oB = 1.0f / (1.0f + __expf(-lB));
    if (haveB) {
        *reinterpret_cast<float2*>(out + i0) = make_float2(oA, oB);
    } else {
        out[i0] = oA;
    }
}

// ---------------- launch ----------------
extern "C" void kernel_launch(void* const* d_in, const int* in_sizes, int n_in,
                              void* d_out, int out_size)
{
    const float* x = (const float*)d_in[0];
    int B = in_sizes[0] / 8;

    // input order: x, prototypes, Wq, bq, Wk, bk, Wv, bv, Wo, bo,
    //              ln1_g, ln1_b, ln2_g, ln2_b, W1, b1, W2, b2, Wc, bc
    fold_kernel<<<1, 256>>>(
        (const float*)d_in[1],                           // prototypes
        (const float*)d_in[6],  (const float*)d_in[7],   // Wv, bv
        (const float*)d_in[8],  (const float*)d_in[9],   // Wo, bo
        (const float*)d_in[10], (const float*)d_in[11],  // ln1_g, ln1_b
        (const float*)d_in[12], (const float*)d_in[13],  // ln2_g, ln2_b
        (const float*)d_in[14], (const float*)d_in[15],  // W1, b1
        (const float*)d_in[16], (const float*)d_in[17],  // W2, b2
        (const float*)d_in[18], (const float*)d_in[19]); // Wc, bc

    int pairs = (B + 1) / 2;
    fwd_kernel<<<(pairs + 255) / 256, 256>>>(x, (float*)d_out, B);
}